// round 17
// baseline (speedup 1.0000x reference)
#include <cuda_runtime.h>
#include <cstdint>
#include <cstddef>

// Problem constants
#define NTOK   2048
#define DMODEL 2048
#define DFF    8192
#define NEXP   4
#define CAP    2048
#define TSTR   20                  // padded row stride (floats) for ldmatrix tiles

// Pipeline
#define KT     16                  // K elems per stage
#define NS     4                   // stages

// gemm1 stage layout (bytes): A[128][16] + Bg[64][16] + Bu[64][16], stride 20 fl
#define G1_A   0
#define G1_BG  (128 * TSTR * 4)            // 10240
#define G1_BU  (G1_BG + 64 * TSTR * 4)     // 15360
#define G1_STG (G1_BU + 64 * TSTR * 4)     // 20480
#define G1_SMEM (NS * G1_STG)              // 81920

// gemm2 stage layout: A[128][16] + B[128][16]
#define G2_A   0
#define G2_B   (128 * TSTR * 4)            // 10240
#define G2_STG (G2_B + 128 * TSTR * 4)     // 20480
#define G2_SMEM (NS * G2_STG)              // 81920

// ---------------------------------------------------------------------------
// Scratch (static device globals; no allocation anywhere)
// ---------------------------------------------------------------------------
__device__ int   g_cnt[NEXP];
__device__ int   g_list[NEXP * CAP];
__device__ int   g_tok_e[NTOK * 2];
__device__ int   g_tok_r[NTOK * 2];
__device__ float g_tok_v[NTOK * 2];
__device__ __align__(256) float g_H[(size_t)NEXP * CAP * DFF];       // 268 MB (tf32)
__device__ __align__(256) float g_O[(size_t)NEXP * CAP * DMODEL];    //  67 MB
__device__ __align__(256) float g_xc [(size_t)NTOK * DMODEL];        //  16 MB (tf32)
__device__ __align__(256) float g_Wgt[(size_t)NEXP * DFF * DMODEL];  // 256 MB [E][F][D] tf32
__device__ __align__(256) float g_Wut[(size_t)NEXP * DFF * DMODEL];  // 256 MB [E][F][D] tf32
__device__ __align__(256) float g_Wdt[(size_t)NEXP * DMODEL * DFF];  // 256 MB [E][D][F] tf32

// ---------------------------------------------------------------------------
// PTX helpers
// ---------------------------------------------------------------------------
__device__ __forceinline__ unsigned f2tf(float x) {
    unsigned u;
    asm("cvt.rna.tf32.f32 %0, %1;" : "=r"(u) : "f"(x));
    return u;
}

__device__ __forceinline__ void mma_tf32(float* c, const unsigned* a, const unsigned* b) {
    asm volatile(
        "mma.sync.aligned.m16n8k8.row.col.f32.tf32.tf32.f32 "
        "{%0,%1,%2,%3}, {%4,%5,%6,%7}, {%8,%9}, {%0,%1,%2,%3};"
        : "+f"(c[0]), "+f"(c[1]), "+f"(c[2]), "+f"(c[3])
        : "r"(a[0]), "r"(a[1]), "r"(a[2]), "r"(a[3]), "r"(b[0]), "r"(b[1]));
}

// ldmatrix.x4 on tf32 data viewed as b16 pairs.
__device__ __forceinline__ void ldsm4(unsigned* r, unsigned addr) {
    asm volatile("ldmatrix.sync.aligned.m8n8.x4.shared.b16 {%0,%1,%2,%3}, [%4];"
        : "=r"(r[0]), "=r"(r[1]), "=r"(r[2]), "=r"(r[3]) : "r"(addr));
}

__device__ __forceinline__ unsigned smem_u32(const void* p) {
    return (unsigned)__cvta_generic_to_shared(p);
}

#define CPA(dst, src, p) \
    asm volatile("cp.async.cg.shared.global [%0], [%1], 16, %2;" \
        :: "r"(dst), "l"(src), "r"((p) ? 16 : 0) : "memory")
#define CPA_COMMIT() asm volatile("cp.async.commit_group;" ::: "memory")
#define CPA_WAIT2()  asm volatile("cp.async.wait_group 2;" ::: "memory")

// ---------------------------------------------------------------------------
// Kernel 0: reset per-expert counters
// ---------------------------------------------------------------------------
__global__ void init_kernel() {
    if (threadIdx.x < NEXP) g_cnt[threadIdx.x] = 0;
}

// ---------------------------------------------------------------------------
// Kernel C1: elementwise tf32 (rna) rounding
// ---------------------------------------------------------------------------
__global__ void cvt_kernel(const float4* __restrict__ in, float4* __restrict__ out, int n4) {
    int stride = gridDim.x * blockDim.x;
    for (int i = blockIdx.x * blockDim.x + threadIdx.x; i < n4; i += stride) {
        float4 v = in[i];
        float4 r;
        r.x = __uint_as_float(f2tf(v.x));
        r.y = __uint_as_float(f2tf(v.y));
        r.z = __uint_as_float(f2tf(v.z));
        r.w = __uint_as_float(f2tf(v.w));
        out[i] = r;
    }
}

// ---------------------------------------------------------------------------
// Kernel C2: fused tf32-round + transpose  in[R][C] -> out[C][R]  (per expert z)
// ---------------------------------------------------------------------------
__global__ void cvtT_kernel(const float* __restrict__ in, float* __restrict__ out,
                            int R, int C) {
    __shared__ float t[32][33];
    const size_t eo = (size_t)blockIdx.z * R * C;
    in += eo; out += eo;
    const int c0 = blockIdx.x * 32, r0 = blockIdx.y * 32;
    #pragma unroll
    for (int k = 0; k < 4; k++)
        t[threadIdx.y + 8*k][threadIdx.x] =
            in[(size_t)(r0 + threadIdx.y + 8*k) * C + c0 + threadIdx.x];
    __syncthreads();
    #pragma unroll
    for (int k = 0; k < 4; k++)
        out[(size_t)(c0 + threadIdx.y + 8*k) * R + r0 + threadIdx.x] =
            __uint_as_float(f2tf(t[threadIdx.x][threadIdx.y + 8*k]));
}

// ---------------------------------------------------------------------------
// Kernel 1: router
// ---------------------------------------------------------------------------
__global__ void router_kernel(const float* __restrict__ x, const float* __restrict__ Wr) {
    const int t = blockIdx.x;
    const float* xr = x + (size_t)t * DMODEL;

    float a0 = 0.f, a1 = 0.f, a2 = 0.f, a3 = 0.f;
    for (int d = threadIdx.x; d < DMODEL; d += 128) {
        float xv = xr[d];
        const float* w = Wr + d * NEXP;
        a0 += xv * w[0]; a1 += xv * w[1]; a2 += xv * w[2]; a3 += xv * w[3];
    }
    #pragma unroll
    for (int o = 16; o > 0; o >>= 1) {
        a0 += __shfl_xor_sync(0xffffffffu, a0, o);
        a1 += __shfl_xor_sync(0xffffffffu, a1, o);
        a2 += __shfl_xor_sync(0xffffffffu, a2, o);
        a3 += __shfl_xor_sync(0xffffffffu, a3, o);
    }
    __shared__ float red[4][NEXP];
    const int warp = threadIdx.x >> 5;
    if ((threadIdx.x & 31) == 0) {
        red[warp][0] = a0; red[warp][1] = a1; red[warp][2] = a2; red[warp][3] = a3;
    }
    __syncthreads();
    if (threadIdx.x == 0) {
        float l[NEXP];
        #pragma unroll
        for (int e = 0; e < NEXP; e++)
            l[e] = red[0][e] + red[1][e] + red[2][e] + red[3][e];
        float mx = l[0];
        #pragma unroll
        for (int e = 1; e < NEXP; e++) mx = fmaxf(mx, l[e]);
        float p[NEXP]; float s = 0.f;
        #pragma unroll
        for (int e = 0; e < NEXP; e++) { p[e] = __expf(l[e] - mx); s += p[e]; }
        float inv = 1.f / s;
        #pragma unroll
        for (int e = 0; e < NEXP; e++) p[e] *= inv;
        int e0 = 0;
        #pragma unroll
        for (int e = 1; e < NEXP; e++) if (p[e] > p[e0]) e0 = e;
        int e1 = (e0 == 0) ? 1 : 0;
        #pragma unroll
        for (int e = 0; e < NEXP; e++) if (e != e0 && p[e] > p[e1]) e1 = e;

        int s0 = atomicAdd(&g_cnt[e0], 1);
        g_list[e0 * CAP + s0] = t;
        g_tok_e[2*t + 0] = e0; g_tok_r[2*t + 0] = s0; g_tok_v[2*t + 0] = p[e0];

        int s1 = atomicAdd(&g_cnt[e1], 1);
        g_list[e1 * CAP + s1] = t;
        g_tok_e[2*t + 1] = e1; g_tok_r[2*t + 1] = s1; g_tok_v[2*t + 1] = p[e1];
    }
}

// ---------------------------------------------------------------------------
// Kernel 2: fused dual GEMM, cp.async 4-stage pipeline, all-ldmatrix consumer.
// Tile 128(M)x64(N)x16(K); 8 warps (4M x 2N), warp tile 32x32.
// B tiles stored [n][k] (stride 20 floats) so B fragments come via ldmatrix.x4.
// ---------------------------------------------------------------------------
__global__ __launch_bounds__(256, 2) void gemm1_kernel() {
    const int e   = blockIdx.z;
    const int mt  = blockIdx.x;   // fastest
    const int nt  = blockIdx.y;
    const int cnt = g_cnt[e];
    if (mt * 128 >= cnt) return;

    extern __shared__ char smem[];
    const unsigned sb = smem_u32(smem);

    const int tid  = threadIdx.x;
    const int lane = tid & 31;
    const int warp = tid >> 5;
    const int gid  = lane >> 2;
    const int tig  = lane & 3;
    const int wmb  = (warp & 3) * 32;
    const int wnb  = (warp >> 2) * 32;

    // ---- producer mapping: 4 x 16B cp.async per thread per stage ----
    // threads 0-127: A row tid (16 floats = 4 chunks)
    // threads 128-191: Bg row tid-128; threads 192-255: Bu row tid-192
    const float* gsrc;
    unsigned     sdst;
    bool         gpred = true;
    if (tid < 128) {
        const int m = mt * 128 + tid;
        gpred = (m < cnt);
        gsrc  = gpred ? (g_xc + (size_t)g_list[e*CAP + m] * DMODEL) : g_xc;
        sdst  = (unsigned)(G1_A + tid * (TSTR*4));
    } else if (tid < 192) {
        const int row = tid - 128;
        gsrc  = g_Wgt + ((size_t)e*DFF + (size_t)nt*64 + row) * DMODEL;
        sdst  = (unsigned)(G1_BG + row * (TSTR*4));
    } else {
        const int row = tid - 192;
        gsrc  = g_Wut + ((size_t)e*DFF + (size_t)nt*64 + row) * DMODEL;
        sdst  = (unsigned)(G1_BU + row * (TSTR*4));
    }

#define G1_ISSUE(kt, slot) do {                                          \
        unsigned b_ = sb + (slot) * G1_STG + sdst;                       \
        const float* s_ = gsrc + (size_t)(kt) * KT;                      \
        CPA(b_,      s_,      gpred);                                    \
        CPA(b_ + 16, s_ + 4,  gpred);                                    \
        CPA(b_ + 32, s_ + 8,  gpred);                                    \
        CPA(b_ + 48, s_ + 12, gpred);                                    \
        CPA_COMMIT();                                                    \
    } while (0)

    // ---- consumer fragment addressing ----
    const unsigned a_lo = (((lane & 7) + ((lane >> 3) & 1) * 8) * TSTR) * 4u
                        + ((lane >> 4) << 4);
    const unsigned b_lo = (((lane & 7) + ((lane >> 4) & 1) * 8) * TSTR) * 4u
                        + (((lane >> 3) & 1) << 4);

    float cg[2][4][4], cu[2][4][4];
    #pragma unroll
    for (int i = 0; i < 2; i++)
        #pragma unroll
        for (int j = 0; j < 4; j++)
            #pragma unroll
            for (int r = 0; r < 4; r++) { cg[i][j][r] = 0.f; cu[i][j][r] = 0.f; }

    const int NKT = DMODEL / KT;   // 128
    G1_ISSUE(0, 0); G1_ISSUE(1, 1); G1_ISSUE(2, 2);

    for (int kt = 0; kt < NKT; kt++) {
        CPA_WAIT2();
        __syncthreads();
        if (kt + NS - 1 < NKT) G1_ISSUE(kt + NS - 1, (kt + NS - 1) & (NS - 1));
        else CPA_COMMIT();

        const int slot = kt & (NS - 1);
        const unsigned st = sb + slot * G1_STG;
        const unsigned ab = st + G1_A  + (unsigned)(wmb * (TSTR*4)) + a_lo;
        const unsigned gb = st + G1_BG + (unsigned)(wnb * (TSTR*4)) + b_lo;
        const unsigned ub = st + G1_BU + (unsigned)(wnb * (TSTR*4)) + b_lo;

        #pragma unroll
        for (int kk = 0; kk < KT; kk += 8) {
            unsigned a[2][4], bG[2][4], bU[2][4];
            ldsm4(a[0], ab + (unsigned)(kk*4));
            ldsm4(a[1], ab + (unsigned)(kk*4) + 16u * (TSTR*4));
            ldsm4(bG[0], gb + (unsigned)(kk*4));                      // nf 0,1
            ldsm4(bG[1], gb + (unsigned)(kk*4) + 16u * (TSTR*4));     // nf 2,3
            ldsm4(bU[0], ub + (unsigned)(kk*4));
            ldsm4(bU[1], ub + (unsigned)(kk*4) + 16u * (TSTR*4));
            #pragma unroll
            for (int mf = 0; mf < 2; mf++)
                #pragma unroll
                for (int np = 0; np < 2; np++) {
                    mma_tf32(cg[mf][np*2+0], a[mf], &bG[np][0]);
                    mma_tf32(cg[mf][np*2+1], a[mf], &bG[np][2]);
                    mma_tf32(cu[mf][np*2+0], a[mf], &bU[np][0]);
                    mma_tf32(cu[mf][np*2+1], a[mf], &bU[np][2]);
                }
        }
    }
#undef G1_ISSUE

    // epilogue: H = tf32(silu(g) * u); padded rows produce exactly 0.
    float* Hbase = g_H + ((size_t)e*CAP + (size_t)mt*128) * DFF + (size_t)nt*64;
    #pragma unroll
    for (int mf = 0; mf < 2; mf++) {
        #pragma unroll
        for (int nf = 0; nf < 4; nf++) {
            int r0 = wmb + mf*16 + gid;
            int c0 = wnb + nf*8 + tig*2;
            float* p0 = Hbase + (size_t)r0 * DFF + c0;
            float* p1 = Hbase + (size_t)(r0 + 8) * DFF + c0;
            float g0 = cg[mf][nf][0], g1 = cg[mf][nf][1];
            float g2 = cg[mf][nf][2], g3 = cg[mf][nf][3];
            p0[0] = __uint_as_float(f2tf((g0 / (1.f + __expf(-g0))) * cu[mf][nf][0]));
            p0[1] = __uint_as_float(f2tf((g1 / (1.f + __expf(-g1))) * cu[mf][nf][1]));
            p1[0] = __uint_as_float(f2tf((g2 / (1.f + __expf(-g2))) * cu[mf][nf][2]));
            p1[1] = __uint_as_float(f2tf((g3 / (1.f + __expf(-g3))) * cu[mf][nf][3]));
        }
    }
}

// ---------------------------------------------------------------------------
// Kernel 3: O = H @ Wdt^T, cp.async 4-stage pipeline, all-ldmatrix consumer.
// Tile 128(M)x128(N)x16(K); 8 warps (2M x 4N), warp tile 64x32.
// ---------------------------------------------------------------------------
__global__ __launch_bounds__(256, 2) void gemm2_kernel() {
    const int e   = blockIdx.z;
    const int mt  = blockIdx.x;   // fastest
    const int nt  = blockIdx.y;
    const int cnt = g_cnt[e];
    if (mt * 128 >= cnt) return;

    extern __shared__ char smem[];
    const unsigned sb = smem_u32(smem);

    const int tid  = threadIdx.x;
    const int lane = tid & 31;
    const int warp = tid >> 5;
    const int gid  = lane >> 2;
    const int tig  = lane & 3;
    const int wmb  = (warp & 1) * 64;
    const int wnb  = (warp >> 1) * 32;

    // producer: threads 0-127 A row tid; 128-255 B row tid-128
    const float* gsrc;
    unsigned     sdst;
    if (tid < 128) {
        gsrc = g_H + ((size_t)e*CAP + (size_t)mt*128 + tid) * DFF;
        sdst = (unsigned)(G2_A + tid * (TSTR*4));
    } else {
        const int row = tid - 128;
        gsrc = g_Wdt + ((size_t)e*DMODEL + (size_t)nt*128 + row) * DFF;
        sdst = (unsigned)(G2_B + row * (TSTR*4));
    }

#define G2_ISSUE(kt, slot) do {                                          \
        unsigned b_ = sb + (slot) * G2_STG + sdst;                       \
        const float* s_ = gsrc + (size_t)(kt) * KT;                      \
        CPA(b_,      s_,      true);                                     \
        CPA(b_ + 16, s_ + 4,  true);                                     \
        CPA(b_ + 32, s_ + 8,  true);                                     \
        CPA(b_ + 48, s_ + 12, true);                                     \
        CPA_COMMIT();                                                    \
    } while (0)

    const unsigned a_lo = (((lane & 7) + ((lane >> 3) & 1) * 8) * TSTR) * 4u
                        + ((lane >> 4) << 4);
    const unsigned b_lo = (((lane & 7) + ((lane >> 4) & 1) * 8) * TSTR) * 4u
                        + (((lane >> 3) & 1) << 4);

    float c[4][4][4];
    #pragma unroll
    for (int i = 0; i < 4; i++)
        #pragma unroll
        for (int j = 0; j < 4; j++)
            #pragma unroll
            for (int r = 0; r < 4; r++) c[i][j][r] = 0.f;

    const int NKT = DFF / KT;   // 512
    G2_ISSUE(0, 0); G2_ISSUE(1, 1); G2_ISSUE(2, 2);

    for (int kt = 0; kt < NKT; kt++) {
        CPA_WAIT2();
        __syncthreads();
        if (kt + NS - 1 < NKT) G2_ISSUE(kt + NS - 1, (kt + NS - 1) & (NS - 1));
        else CPA_COMMIT();

        const int slot = kt & (NS - 1);
        const unsigned st = sb + slot * G2_STG;
        const unsigned ab = st + G2_A + (unsigned)(wmb * (TSTR*4)) + a_lo;
        const unsigned bb = st + G2_B + (unsigned)(wnb * (TSTR*4)) + b_lo;

        #pragma unroll
        for (int kk = 0; kk < KT; kk += 8) {
            unsigned a[4][4], b[2][4];
            #pragma unroll
            for (int mf = 0; mf < 4; mf++)
                ldsm4(a[mf], ab + (unsigned)(kk*4) + (unsigned)(mf * 16 * (TSTR*4)));
            ldsm4(b[0], bb + (unsigned)(kk*4));                       // nf 0,1
            ldsm4(b[1], bb + (unsigned)(kk*4) + 16u * (TSTR*4));      // nf 2,3
            #pragma unroll
            for (int mf = 0; mf < 4; mf++)
                #pragma unroll
                for (int np = 0; np < 2; np++) {
                    mma_tf32(c[mf][np*2+0], a[mf], &b[np][0]);
                    mma_tf32(c[mf][np*2+1], a[mf], &b[np][2]);
                }
        }
    }
#undef G2_ISSUE

    float* Obase = g_O + ((size_t)e*CAP + (size_t)mt*128) * DMODEL + (size_t)nt*128;
    #pragma unroll
    for (int mf = 0; mf < 4; mf++) {
        #pragma unroll
        for (int nf = 0; nf < 4; nf++) {
            int r0 = wmb + mf*16 + gid;
            int c0 = wnb + nf*8 + tig*2;
            float* p0 = Obase + (size_t)r0 * DMODEL + c0;
            float* p1 = Obase + (size_t)(r0 + 8) * DMODEL + c0;
            p0[0] = c[mf][nf][0]; p0[1] = c[mf][nf][1];
            p1[0] = c[mf][nf][2]; p1[1] = c[mf][nf][3];
        }
    }
}

// ---------------------------------------------------------------------------
// Kernel 4: combine.  out[t] = v0*O[e0][r0] + v1*O[e1][r1]
// ---------------------------------------------------------------------------
__global__ void combine_kernel(float* __restrict__ out) {
    const int t  = blockIdx.x;
    const int e0 = g_tok_e[2*t + 0], e1 = g_tok_e[2*t + 1];
    const int r0 = g_tok_r[2*t + 0], r1 = g_tok_r[2*t + 1];
    const float v0 = g_tok_v[2*t + 0], v1 = g_tok_v[2*t + 1];
    const float4* o0 = (const float4*)(g_O + ((size_t)e0*CAP + r0) * DMODEL);
    const float4* o1 = (const float4*)(g_O + ((size_t)e1*CAP + r1) * DMODEL);
    float4* dst = (float4*)(out + (size_t)t * DMODEL);
    for (int i = threadIdx.x; i < DMODEL / 4; i += blockDim.x) {
        float4 a = o0[i], b = o1[i];
        float4 r;
        r.x = v0 * a.x + v1 * b.x;
        r.y = v0 * a.y + v1 * b.y;
        r.z = v0 * a.z + v1 * b.z;
        r.w = v0 * a.w + v1 * b.w;
        dst[i] = r;
    }
}

// ---------------------------------------------------------------------------
// Launch
// ---------------------------------------------------------------------------
extern "C" void kernel_launch(void* const* d_in, const int* in_sizes, int n_in,
                              void* d_out, int out_size) {
    const float* x  = (const float*)d_in[0];
    const float* Wr = (const float*)d_in[1];
    const float* Wg = (const float*)d_in[2];   // [E,D,F]
    const float* Wu = (const float*)d_in[3];   // [E,D,F]
    const float* Wd = (const float*)d_in[4];   // [E,F,D]
    float* out = (float*)d_out;

    cudaFuncSetAttribute(gemm1_kernel, cudaFuncAttributeMaxDynamicSharedMemorySize, G1_SMEM);
    cudaFuncSetAttribute(gemm2_kernel, cudaFuncAttributeMaxDynamicSharedMemorySize, G2_SMEM);

    float *xc, *wgt, *wut, *wdt;
    cudaGetSymbolAddress((void**)&xc,  g_xc);
    cudaGetSymbolAddress((void**)&wgt, g_Wgt);
    cudaGetSymbolAddress((void**)&wut, g_Wut);
    cudaGetSymbolAddress((void**)&wdt, g_Wdt);

    init_kernel<<<1, 32>>>();
    router_kernel<<<NTOK, 128>>>(x, Wr);

    // tf32 rounding: x linear; weights fused round+transpose to K-contiguous rows
    cvt_kernel<<<4096, 256>>>((const float4*)x, (float4*)xc, NTOK * DMODEL / 4);
    {
        dim3 blk(32, 8);
        dim3 gGU(DFF / 32, DMODEL / 32, NEXP);   // Wg/Wu: [D][F] -> [F][D]
        cvtT_kernel<<<gGU, blk>>>(Wg, wgt, DMODEL, DFF);
        cvtT_kernel<<<gGU, blk>>>(Wu, wut, DMODEL, DFF);
        dim3 gD(DMODEL / 32, DFF / 32, NEXP);    // Wd: [F][D] -> [D][F]
        cvtT_kernel<<<gD, blk>>>(Wd, wdt, DFF, DMODEL);
    }

    // mt fastest: one wave spans all M tiles -> B tiles stream from DRAM once
    dim3 grid1(CAP / 128, DFF / 64, NEXP);     // (16, 128, 4)
    gemm1_kernel<<<grid1, 256, G1_SMEM>>>();

    dim3 grid2(CAP / 128, DMODEL / 128, NEXP); // (16, 16, 4)
    gemm2_kernel<<<grid2, 256, G2_SMEM>>>();

    combine_kernel<<<NTOK, 256>>>(out);
}